// round 10
// baseline (speedup 1.0000x reference)
#include <cuda_runtime.h>

#define HH 512
#define WW 512
#define NPIX (HH*WW)
#define BS 16

// Per-(batch,direction) projection params
__device__ float g_params[BS * 2][12];
__device__ int g_maskmode;  // 0 = 4-byte elements, 1 = 1-byte elements

// 2x2 depth patches: plane img = b (depth0) or 16+b (depth1).
// patch[j] = (d[j], d[j+1], d[j+512], d[j+513]) — one LDG.128 = all 4 bilinear taps.
__device__ float4 g_patch[32u * NPIX];

__global__ void setup_kernel(const float* __restrict__ R0, const float* __restrict__ t0,
                             const float* __restrict__ R1, const float* __restrict__ t1,
                             const float* __restrict__ K,
                             const unsigned int* __restrict__ mask_probe,
                             float* __restrict__ out, int out_size)
{
    int t = threadIdx.x;
    if (t < out_size && t < 32) out[t] = 0.0f;

    if (t == 0) {
        bool sawFloat = false, sawBig = false;
        for (int i = 0; i < 16; i++) {
            unsigned int w = mask_probe[i];
            if (w == 0x3f800000u) sawFloat = true;
            else if (w > 1u) sawBig = true;
        }
        g_maskmode = sawFloat ? 0 : (sawBig ? 1 : 0);
    }

    if (t >= 32) return;
    int b = t >> 1;
    int dir = t & 1;

    float k[9];
    #pragma unroll
    for (int i = 0; i < 9; i++) k[i] = K[i];
    float det = k[0]*(k[4]*k[8]-k[5]*k[7]) - k[1]*(k[3]*k[8]-k[5]*k[6]) + k[2]*(k[3]*k[7]-k[4]*k[6]);
    float rdet = 1.0f / det;
    float ki[9];
    ki[0]=(k[4]*k[8]-k[5]*k[7])*rdet; ki[1]=(k[2]*k[7]-k[1]*k[8])*rdet; ki[2]=(k[1]*k[5]-k[2]*k[4])*rdet;
    ki[3]=(k[5]*k[6]-k[3]*k[8])*rdet; ki[4]=(k[0]*k[8]-k[2]*k[6])*rdet; ki[5]=(k[2]*k[3]-k[0]*k[5])*rdet;
    ki[6]=(k[3]*k[7]-k[4]*k[6])*rdet; ki[7]=(k[1]*k[6]-k[0]*k[7])*rdet; ki[8]=(k[0]*k[4]-k[1]*k[3])*rdet;

    const float* Ra = dir ? (R1 + 9*b) : (R0 + 9*b);
    const float* Rb = dir ? (R0 + 9*b) : (R1 + 9*b);
    const float* ta = dir ? (t1 + 3*b) : (t0 + 3*b);
    const float* tb = dir ? (t0 + 3*b) : (t1 + 3*b);

    float M3[9];
    #pragma unroll
    for (int i = 0; i < 3; i++)
        #pragma unroll
        for (int j = 0; j < 3; j++) {
            float s = 0.0f;
            #pragma unroll
            for (int d = 0; d < 3; d++) s += Rb[i*3+d] * Ra[j*3+d];
            M3[i*3+j] = s;
        }
    float M[9];
    #pragma unroll
    for (int i = 0; i < 3; i++)
        #pragma unroll
        for (int j = 0; j < 3; j++) {
            float s = 0.0f;
            #pragma unroll
            for (int d = 0; d < 3; d++) s += k[i*3+d] * M3[d*3+j];
            M[i*3+j] = s;
        }
    float c[3];
    #pragma unroll
    for (int i = 0; i < 3; i++) {
        float s = 0.0f;
        #pragma unroll
        for (int d = 0; d < 3; d++) s += k[i*3+d]*tb[d] - M[i*3+d]*ta[d];
        c[i] = s;
    }
    float G[9];
    #pragma unroll
    for (int i = 0; i < 3; i++)
        #pragma unroll
        for (int j = 0; j < 3; j++) {
            float s = 0.0f;
            #pragma unroll
            for (int d = 0; d < 3; d++) s += M[i*3+d] * ki[d*3+j];
            G[i*3+j] = s;
        }

    float* P = g_params[t];
    P[0] = G[0]; P[1] = G[3]; P[2] = G[6];
    P[3] = G[1]; P[4] = G[4]; P[5] = G[7];
    P[6] = G[2]; P[7] = G[5]; P[8] = G[8];
    P[9] = c[0]; P[10] = c[1]; P[11] = c[2];
}

// Build 2x2 patch planes. grid(256, 16, 2), block 256. Pure streaming.
__global__ __launch_bounds__(256)
void patch_kernel(const float* __restrict__ d0, const float* __restrict__ d1)
{
    const int b = blockIdx.y;
    const int z = blockIdx.z;                    // 0 = depth0 planes, 1 = depth1 planes
    const float* src = (z ? d1 : d0) + b * NPIX;
    const int img = z * BS + b;

    int qv = blockIdx.x * blockDim.x + threadIdx.x;   // quad index 0..65535
    int p  = qv << 2;

    float4 cur = __ldcs((const float4*)src + qv);
    int pn = p + WW;
    if (pn >= NPIX) pn = p;                      // last row: repeat (patches there unread)
    float4 nxt = __ldcs((const float4*)src + (pn >> 2));
    float ce = __ldg(src + min(p  + 4, NPIX - 1));   // only feeds x=511 patch (unread)
    float ne = __ldg(src + min(pn + 4, NPIX - 1));

    float4* o = g_patch + (size_t)img * NPIX + p;
    o[0] = make_float4(cur.x, cur.y, nxt.x, nxt.y);
    o[1] = make_float4(cur.y, cur.z, nxt.y, nxt.z);
    o[2] = make_float4(cur.z, cur.w, nxt.z, nxt.w);
    o[3] = make_float4(cur.w, ce,    nxt.w, ne);
}

__inline__ __device__ float warp_sum(float v) {
    #pragma unroll
    for (int o = 16; o > 0; o >>= 1) v += __shfl_down_sync(0xffffffffu, v, o);
    return v;
}

__inline__ __device__ float fast_rcp(float x) {
    float r;
    asm("rcp.approx.ftz.f32 %0, %1;" : "=f"(r) : "f"(x));
    return r;
}

__inline__ __device__ int load_mask_bits(const void* ms, int mode, int base, int q) {
    if (mode) {
        uchar4 u = __ldcs((const uchar4*)((const unsigned char*)ms + base) + q);
        return (u.x != 0) | ((u.y != 0) << 1) | ((u.z != 0) << 2) | ((u.w != 0) << 3);
    } else {
        uint4 u = __ldcs((const uint4*)((const unsigned int*)ms + base) + q);
        return (u.x != 0u) | ((u.y != 0u) << 1) | ((u.z != 0u) << 2) | ((u.w != 0u) << 3);
    }
}

__global__ __launch_bounds__(256, 5)
void loss_kernel(const float* __restrict__ d0, const float* __restrict__ d1,
                 const float* __restrict__ r0, const float* __restrict__ r1,
                 const void* __restrict__ m0, const void* __restrict__ m1,
                 float* __restrict__ out)
{
    const int b   = blockIdx.y;
    const int dir = blockIdx.z;

    const float* ds = dir ? d1 : d0;
    const float* rs = dir ? r1 : r0;
    const float* rd = dir ? r0 : r1;
    const void*  ms = dir ? m1 : m0;

    // gather dest: dir0 -> depth1 planes (16+b), dir1 -> depth0 planes (b)
    const float4* pp = g_patch + (size_t)(dir ? b : BS + b) * NPIX;

    const float* P = g_params[b*2 + dir];
    const float Au0=P[0], Au1=P[1], Au2=P[2];
    const float Av0=P[3], Av1=P[4], Av2=P[5];
    const float A00=P[6], A01=P[7], A02=P[8];
    const float c0 =P[9], c1 =P[10], c2 =P[11];
    const int mode = g_maskmode;

    const int base  = b * NPIX;
    const int base3 = b * 3 * NPIX;

    const float4* dsv = (const float4*)(ds + base);

    float sd = 0.0f, sr = 0.0f;
    const int nq = NPIX / 4;
    const int stride = gridDim.x * blockDim.x;

    int q = blockIdx.x * blockDim.x + threadIdx.x;
    float4 dep4;
    int mb = 0;
    if (q < nq) {
        dep4 = __ldcs(dsv + q);
        mb = load_mask_bits(ms, mode, base, q);
    }

    for (; q < nq; ) {
        const int p0 = q << 2;
        float dep[4] = {dep4.x, dep4.y, dep4.z, dep4.w};

        const float v  = (float)(p0 >> 9);
        const float u0 = (float)(p0 & 511);
        const float bX = fmaf(Av0, v, A00);
        const float bY = fmaf(Av1, v, A01);
        const float bZ = fmaf(Av2, v, A02);

        // ---- projections (batched, ILP=4); clamp to 510.9995 => taps in-bounds ----
        float Z[4], fx[4], fy[4];
        int i00[4];                    // plane-relative patch index
        #pragma unroll
        for (int i = 0; i < 4; i++) {
            float u = u0 + (float)i;
            float X  = fmaf(dep[i], fmaf(Au0, u, bX), c0);
            float Y  = fmaf(dep[i], fmaf(Au1, u, bY), c1);
            float Zi = fmaf(dep[i], fmaf(Au2, u, bZ), c2);
            Z[i] = Zi;

            float inv = fast_rcp(fmaxf(Zi, 0.0f) + 1e-12f);
            float xs = fmaf(X * inv, 512.0f / 511.0f, -0.5f);
            float ys = fmaf(Y * inv, 512.0f / 511.0f, -0.5f);
            xs = fminf(fmaxf(xs, 0.0f), 510.9995f);
            ys = fminf(fmaxf(ys, 0.0f), 510.9995f);

            float x0f = floorf(xs), y0f = floorf(ys);
            fx[i] = xs - x0f;
            fy[i] = ys - y0f;
            i00[i] = (int)y0f * WW + (int)x0f;
        }

        // ---- prefetch next iteration's coherent loads ----
        const int qn = q + stride;
        float4 dep4n = dep4;
        int mbn = 0;
        if (qn < nq) {
            dep4n = __ldcs(dsv + qn);
            mbn = load_mask_bits(ms, mode, base, qn);
        }

        // ---- depth gathers: ONE LDG.128 per masked pixel (all 4 taps) ----
        float4 g[4];
        #pragma unroll
        for (int i = 0; i < 4; i++) {
            if (mb & (1 << i)) {
                g[i] = __ldg(pp + i00[i]);
            } else {
                g[i] = make_float4(1e30f, 1e30f, 1e30f, 1e30f);
            }
        }

        // ---- clamp test + sparse (~13%) predicated RGB work ----
        #pragma unroll
        for (int i = 0; i < 4; i++) {
            float ofx = 1.0f - fx[i], ofy = 1.0f - fy[i];
            float w00 = ofx*ofy, w01 = fx[i]*ofy, w10 = ofx*fy[i], w11 = fx[i]*fy[i];
            float dsm = w00*g[i].x + w01*g[i].y + w10*g[i].z + w11*g[i].w;
            float ld = fabsf(Z[i] - dsm);
            if (ld < 0.1f) {               // sentinel 1e30 auto-fails
                sd += ld;
                int a00 = i00[i];
                int p = p0 + i;
                float lr = 0.0f;
                #pragma unroll
                for (int cch = 0; cch < 3; cch++) {
                    const int o = base3 + cch * NPIX;
                    float sv = __ldcs(rs + o + p);
                    const float* ch = rd + o + a00;
                    float sm = w00*__ldg(ch)      + w01*__ldg(ch + 1)
                             + w10*__ldg(ch + WW) + w11*__ldg(ch + WW + 1);
                    lr += fabsf(sv - sm);
                }
                sr += lr * (1.0f / 3.0f);
            }
        }

        dep4 = dep4n;
        mb = mbn;
        q = qn;
    }

    sd = warp_sum(sd);
    sr = warp_sum(sr);
    __shared__ float sD[8], sR[8];
    int lane = threadIdx.x & 31, wid = threadIdx.x >> 5;
    if (lane == 0) { sD[wid] = sd; sR[wid] = sr; }
    __syncthreads();
    if (threadIdx.x == 0) {
        float td = 0.0f, tr = 0.0f;
        #pragma unroll
        for (int i = 0; i < 8; i++) { td += sD[i]; tr += sR[i]; }
        const float invN = 1.0f / (float)NPIX;
        atomicAdd(out + b,      td * invN);
        atomicAdd(out + 16 + b, tr * invN);
    }
}

extern "C" void kernel_launch(void* const* d_in, const int* in_sizes, int n_in,
                              void* d_out, int out_size)
{
    const float* depth0 = (const float*)d_in[0];
    const float* depth1 = (const float*)d_in[1];
    const float* R0     = (const float*)d_in[2];
    const float* t0     = (const float*)d_in[3];
    const float* R1     = (const float*)d_in[4];
    const float* t1     = (const float*)d_in[5];
    const float* rgb0   = (const float*)d_in[6];
    const float* rgb1   = (const float*)d_in[7];
    const void*  mask0  = d_in[8];
    const void*  mask1  = d_in[9];
    const float* K      = (const float*)d_in[10];
    float* out = (float*)d_out;

    setup_kernel<<<1, 64>>>(R0, t0, R1, t1, K, (const unsigned int*)mask0, out, out_size);

    dim3 pgrid(256, BS, 2);
    patch_kernel<<<pgrid, 256>>>(depth0, depth1);

    // 46 * 16 * 2 = 1472 blocks ≈ 2 full waves at 5 blocks/SM on 148 SMs.
    dim3 grid(46, BS, 2);
    loss_kernel<<<grid, 256>>>(depth0, depth1, rgb0, rgb1, mask0, mask1, out);
}

// round 16
// speedup vs baseline: 1.4943x; 1.4943x over previous
#include <cuda_runtime.h>
#include <cstring>

#define HH 512
#define WW 512
#define NPIX (HH*WW)
#define BS 16

__device__ float g_params[BS * 2][12];
__device__ int g_maskmode;  // 0 = 4-byte elements, 1 = 1-byte elements

__global__ void setup_kernel(const float* __restrict__ R0, const float* __restrict__ t0,
                             const float* __restrict__ R1, const float* __restrict__ t1,
                             const float* __restrict__ K,
                             const unsigned int* __restrict__ mask_probe,
                             float* __restrict__ out, int out_size)
{
    int t = threadIdx.x;
    if (t < out_size && t < 32) out[t] = 0.0f;

    if (t == 0) {
        bool sawFloat = false, sawBig = false;
        for (int i = 0; i < 16; i++) {
            unsigned int w = mask_probe[i];
            if (w == 0x3f800000u) sawFloat = true;
            else if (w > 1u) sawBig = true;
        }
        g_maskmode = sawFloat ? 0 : (sawBig ? 1 : 0);
    }

    if (t >= 32) return;
    int b = t >> 1;
    int dir = t & 1;

    float k[9];
    #pragma unroll
    for (int i = 0; i < 9; i++) k[i] = K[i];
    float det = k[0]*(k[4]*k[8]-k[5]*k[7]) - k[1]*(k[3]*k[8]-k[5]*k[6]) + k[2]*(k[3]*k[7]-k[4]*k[6]);
    float rdet = 1.0f / det;
    float ki[9];
    ki[0]=(k[4]*k[8]-k[5]*k[7])*rdet; ki[1]=(k[2]*k[7]-k[1]*k[8])*rdet; ki[2]=(k[1]*k[5]-k[2]*k[4])*rdet;
    ki[3]=(k[5]*k[6]-k[3]*k[8])*rdet; ki[4]=(k[0]*k[8]-k[2]*k[6])*rdet; ki[5]=(k[2]*k[3]-k[0]*k[5])*rdet;
    ki[6]=(k[3]*k[7]-k[4]*k[6])*rdet; ki[7]=(k[1]*k[6]-k[0]*k[7])*rdet; ki[8]=(k[0]*k[4]-k[1]*k[3])*rdet;

    const float* Ra = dir ? (R1 + 9*b) : (R0 + 9*b);
    const float* Rb = dir ? (R0 + 9*b) : (R1 + 9*b);
    const float* ta = dir ? (t1 + 3*b) : (t0 + 3*b);
    const float* tb = dir ? (t0 + 3*b) : (t1 + 3*b);

    float M3[9];
    #pragma unroll
    for (int i = 0; i < 3; i++)
        #pragma unroll
        for (int j = 0; j < 3; j++) {
            float s = 0.0f;
            #pragma unroll
            for (int d = 0; d < 3; d++) s += Rb[i*3+d] * Ra[j*3+d];
            M3[i*3+j] = s;
        }
    float M[9];
    #pragma unroll
    for (int i = 0; i < 3; i++)
        #pragma unroll
        for (int j = 0; j < 3; j++) {
            float s = 0.0f;
            #pragma unroll
            for (int d = 0; d < 3; d++) s += k[i*3+d] * M3[d*3+j];
            M[i*3+j] = s;
        }
    float c[3];
    #pragma unroll
    for (int i = 0; i < 3; i++) {
        float s = 0.0f;
        #pragma unroll
        for (int d = 0; d < 3; d++) s += k[i*3+d]*tb[d] - M[i*3+d]*ta[d];
        c[i] = s;
    }
    float G[9];
    #pragma unroll
    for (int i = 0; i < 3; i++)
        #pragma unroll
        for (int j = 0; j < 3; j++) {
            float s = 0.0f;
            #pragma unroll
            for (int d = 0; d < 3; d++) s += M[i*3+d] * ki[d*3+j];
            G[i*3+j] = s;
        }

    float* P = g_params[t];
    P[0] = G[0]; P[1] = G[3]; P[2] = G[6];
    P[3] = G[1]; P[4] = G[4]; P[5] = G[7];
    P[6] = G[2]; P[7] = G[5]; P[8] = G[8];
    P[9] = c[0]; P[10] = c[1]; P[11] = c[2];
}

__inline__ __device__ float warp_sum(float v) {
    #pragma unroll
    for (int o = 16; o > 0; o >>= 1) v += __shfl_down_sync(0xffffffffu, v, o);
    return v;
}

__inline__ __device__ float fast_rcp(float x) {
    float r;
    asm("rcp.approx.ftz.f32 %0, %1;" : "=f"(r) : "f"(x));
    return r;
}

__inline__ __device__ int load_mask_bits(const void* ms, int mode, int base, int q) {
    if (mode) {
        uchar4 u = __ldcs((const uchar4*)((const unsigned char*)ms + base) + q);
        return (u.x != 0) | ((u.y != 0) << 1) | ((u.z != 0) << 2) | ((u.w != 0) << 3);
    } else {
        uint4 u = __ldcs((const uint4*)((const unsigned int*)ms + base) + q);
        return (u.x != 0u) | ((u.y != 0u) << 1) | ((u.z != 0u) << 2) | ((u.w != 0u) << 3);
    }
}

// ============ texture-gather loss kernel ============
// Weights use EXACT (unnudged) fx/fy — identical math to the LDG kernel.
// Only the gather coordinates use fx/fy clamped to [1/64, 63/64], which
// guarantees TLD4 selects the same 2x2 window as our floor() (fixed-point
// snap 1/256 + fp32 coord rounding < 1/64).
__global__ __launch_bounds__(256, 5)
void loss_tex_kernel(const float* __restrict__ d0, const float* __restrict__ d1,
                     const float* __restrict__ r0, const float* __restrict__ r1,
                     const void* __restrict__ m0, const void* __restrict__ m1,
                     cudaTextureObject_t texD0, cudaTextureObject_t texD1,
                     cudaTextureObject_t texR0, cudaTextureObject_t texR1,
                     float* __restrict__ out)
{
    const int b   = blockIdx.y;
    const int dir = blockIdx.z;

    const float* ds = dir ? d1 : d0;
    const float* rs = dir ? r1 : r0;
    const void*  ms = dir ? m1 : m0;
    cudaTextureObject_t texD = dir ? texD0 : texD1;   // gather-dest depth
    cudaTextureObject_t texR = dir ? texR0 : texR1;   // gather-dest rgb

    const float* P = g_params[b*2 + dir];
    const float Au0=P[0], Au1=P[1], Au2=P[2];
    const float Av0=P[3], Av1=P[4], Av2=P[5];
    const float A00=P[6], A01=P[7], A02=P[8];
    const float c0 =P[9], c1 =P[10], c2 =P[11];
    const int mode = g_maskmode;

    const int base  = b * NPIX;
    const int base3 = b * 3 * NPIX;
    const float ybD = 512.0f * (float)b;          // depth plane offset
    const float ybR = 1536.0f * (float)b;         // rgb plane-group offset

    const float4* dsv = (const float4*)(ds + base);

    float sd = 0.0f, sr = 0.0f;
    const int nq = NPIX / 4;
    const int stride = gridDim.x * blockDim.x;

    int q = blockIdx.x * blockDim.x + threadIdx.x;
    float4 dep4;
    int mb = 0;
    if (q < nq) {
        dep4 = __ldcs(dsv + q);
        mb = load_mask_bits(ms, mode, base, q);
    }

    for (; q < nq; ) {
        const int p0 = q << 2;
        float dep[4] = {dep4.x, dep4.y, dep4.z, dep4.w};

        const float v  = (float)(p0 >> 9);
        const float u0 = (float)(p0 & 511);
        const float bX = fmaf(Av0, v, A00);
        const float bY = fmaf(Av1, v, A01);
        const float bZ = fmaf(Av2, v, A02);

        float Z[4], fx[4], fy[4], tx[4], ty[4];
        #pragma unroll
        for (int i = 0; i < 4; i++) {
            float u = u0 + (float)i;
            float X  = fmaf(dep[i], fmaf(Au0, u, bX), c0);
            float Y  = fmaf(dep[i], fmaf(Au1, u, bY), c1);
            float Zi = fmaf(dep[i], fmaf(Au2, u, bZ), c2);
            Z[i] = Zi;

            float inv = fast_rcp(fmaxf(Zi, 0.0f) + 1e-12f);
            float xs = fmaf(X * inv, 512.0f / 511.0f, -0.5f);
            float ys = fmaf(Y * inv, 512.0f / 511.0f, -0.5f);
            xs = fminf(fmaxf(xs, 0.0f), 510.9995f);
            ys = fminf(fmaxf(ys, 0.0f), 510.9995f);

            float x0f = floorf(xs), y0f = floorf(ys);
            float fxi = xs - x0f, fyi = ys - y0f;
            fx[i] = fxi;                          // EXACT weights (match LDG kernel)
            fy[i] = fyi;
            // Nudged coordinate ONLY for window selection:
            float cfx = fminf(fmaxf(fxi, 0.015625f), 0.984375f);
            float cfy = fminf(fmaxf(fyi, 0.015625f), 0.984375f);
            tx[i] = x0f + cfx + 0.5f;             // i0 = floor(tx-0.5) = x0 guaranteed
            ty[i] = y0f + cfy + 0.5f;
        }

        // ---- prefetch next iteration's coherent loads ----
        const int qn = q + stride;
        float4 dep4n = dep4;
        int mbn = 0;
        if (qn < nq) {
            dep4n = __ldcs(dsv + qn);
            mbn = load_mask_bits(ms, mode, base, qn);
        }

        // ---- depth: ONE tex2Dgather per masked pixel (all 4 taps) ----
        float4 g[4];
        #pragma unroll
        for (int i = 0; i < 4; i++) {
            if (mb & (1 << i)) {
                g[i] = tex2Dgather<float4>(texD, tx[i], ty[i] + ybD, 0);
            } else {
                g[i] = make_float4(1e30f, 1e30f, 1e30f, 1e30f);
            }
        }

        // ---- clamp test + sparse rgb via tex2Dgather ----
        #pragma unroll
        for (int i = 0; i < 4; i++) {
            float ofx = 1.0f - fx[i], ofy = 1.0f - fy[i];
            float w00 = ofx*ofy, w01 = fx[i]*ofy, w10 = ofx*fy[i], w11 = fx[i]*fy[i];
            // gather component order: x=(i0,j1) y=(i1,j1) z=(i1,j0) w=(i0,j0)
            float dsm = w00*g[i].w + w01*g[i].z + w10*g[i].x + w11*g[i].y;
            float ld = fabsf(Z[i] - dsm);
            if (ld < 0.1f) {
                sd += ld;
                int p = p0 + i;
                float lr = 0.0f;
                #pragma unroll
                for (int cch = 0; cch < 3; cch++) {
                    float sv = __ldcs(rs + base3 + cch * NPIX + p);
                    float4 gc = tex2Dgather<float4>(texR, tx[i], ty[i] + ybR + 512.0f*(float)cch, 0);
                    float sm = w00*gc.w + w01*gc.z + w10*gc.x + w11*gc.y;
                    lr += fabsf(sv - sm);
                }
                sr += lr * (1.0f / 3.0f);
            }
        }

        dep4 = dep4n;
        mb = mbn;
        q = qn;
    }

    sd = warp_sum(sd);
    sr = warp_sum(sr);
    __shared__ float sD[8], sR[8];
    int lane = threadIdx.x & 31, wid = threadIdx.x >> 5;
    if (lane == 0) { sD[wid] = sd; sR[wid] = sr; }
    __syncthreads();
    if (threadIdx.x == 0) {
        float td = 0.0f, tr = 0.0f;
        #pragma unroll
        for (int i = 0; i < 8; i++) { td += sD[i]; tr += sR[i]; }
        const float invN = 1.0f / (float)NPIX;
        atomicAdd(out + b,      td * invN);
        atomicAdd(out + 16 + b, tr * invN);
    }
}

// ============ fallback: proven R9 LDG kernel ============
__global__ __launch_bounds__(256, 5)
void loss_kernel(const float* __restrict__ d0, const float* __restrict__ d1,
                 const float* __restrict__ r0, const float* __restrict__ r1,
                 const void* __restrict__ m0, const void* __restrict__ m1,
                 float* __restrict__ out)
{
    const int b   = blockIdx.y;
    const int dir = blockIdx.z;

    const float* ds = dir ? d1 : d0;
    const float* dd = dir ? d0 : d1;
    const float* rs = dir ? r1 : r0;
    const float* rd = dir ? r0 : r1;
    const void*  ms = dir ? m1 : m0;

    const float* P = g_params[b*2 + dir];
    const float Au0=P[0], Au1=P[1], Au2=P[2];
    const float Av0=P[3], Av1=P[4], Av2=P[5];
    const float A00=P[6], A01=P[7], A02=P[8];
    const float c0 =P[9], c1 =P[10], c2 =P[11];
    const int mode = g_maskmode;

    const int base  = b * NPIX;
    const int base3 = b * 3 * NPIX;
    const float4* dsv = (const float4*)(ds + base);

    float sd = 0.0f, sr = 0.0f;
    const int nq = NPIX / 4;
    const int stride = gridDim.x * blockDim.x;

    int q = blockIdx.x * blockDim.x + threadIdx.x;
    float4 dep4;
    int mb = 0;
    if (q < nq) {
        dep4 = __ldcs(dsv + q);
        mb = load_mask_bits(ms, mode, base, q);
    }

    for (; q < nq; ) {
        const int p0 = q << 2;
        float dep[4] = {dep4.x, dep4.y, dep4.z, dep4.w};

        const float v  = (float)(p0 >> 9);
        const float u0 = (float)(p0 & 511);
        const float bX = fmaf(Av0, v, A00);
        const float bY = fmaf(Av1, v, A01);
        const float bZ = fmaf(Av2, v, A02);

        float Z[4], fx[4], fy[4];
        int i00[4];
        #pragma unroll
        for (int i = 0; i < 4; i++) {
            float u = u0 + (float)i;
            float X  = fmaf(dep[i], fmaf(Au0, u, bX), c0);
            float Y  = fmaf(dep[i], fmaf(Au1, u, bY), c1);
            float Zi = fmaf(dep[i], fmaf(Au2, u, bZ), c2);
            Z[i] = Zi;

            float inv = fast_rcp(fmaxf(Zi, 0.0f) + 1e-12f);
            float xs = fmaf(X * inv, 512.0f / 511.0f, -0.5f);
            float ys = fmaf(Y * inv, 512.0f / 511.0f, -0.5f);
            xs = fminf(fmaxf(xs, 0.0f), 510.9995f);
            ys = fminf(fmaxf(ys, 0.0f), 510.9995f);

            float x0f = floorf(xs), y0f = floorf(ys);
            fx[i] = xs - x0f;
            fy[i] = ys - y0f;
            i00[i] = base + (int)y0f * WW + (int)x0f;
        }

        const int qn = q + stride;
        float4 dep4n = dep4;
        int mbn = 0;
        if (qn < nq) {
            dep4n = __ldcs(dsv + qn);
            mbn = load_mask_bits(ms, mode, base, qn);
        }

        float g00[4], g01[4], g10[4], g11[4];
        #pragma unroll
        for (int i = 0; i < 4; i++) {
            if (mb & (1 << i)) {
                const float* a = dd + i00[i];
                g00[i] = __ldg(a);
                g01[i] = __ldg(a + 1);
                g10[i] = __ldg(a + WW);
                g11[i] = __ldg(a + WW + 1);
            } else {
                g00[i] = g01[i] = g10[i] = g11[i] = 1e30f;
            }
        }

        #pragma unroll
        for (int i = 0; i < 4; i++) {
            float ofx = 1.0f - fx[i], ofy = 1.0f - fy[i];
            float w00 = ofx*ofy, w01 = fx[i]*ofy, w10 = ofx*fy[i], w11 = fx[i]*fy[i];
            float dsm = w00*g00[i] + w01*g01[i] + w10*g10[i] + w11*g11[i];
            float ld = fabsf(Z[i] - dsm);
            if (ld < 0.1f) {
                sd += ld;
                int a00 = i00[i] - base;
                int p = p0 + i;
                float lr = 0.0f;
                #pragma unroll
                for (int cch = 0; cch < 3; cch++) {
                    const int o = base3 + cch * NPIX;
                    float sv = __ldcs(rs + o + p);
                    const float* ch = rd + o + a00;
                    float sm = w00*__ldg(ch)      + w01*__ldg(ch + 1)
                             + w10*__ldg(ch + WW) + w11*__ldg(ch + WW + 1);
                    lr += fabsf(sv - sm);
                }
                sr += lr * (1.0f / 3.0f);
            }
        }

        dep4 = dep4n;
        mb = mbn;
        q = qn;
    }

    sd = warp_sum(sd);
    sr = warp_sum(sr);
    __shared__ float sD[8], sR[8];
    int lane = threadIdx.x & 31, wid = threadIdx.x >> 5;
    if (lane == 0) { sD[wid] = sd; sR[wid] = sr; }
    __syncthreads();
    if (threadIdx.x == 0) {
        float td = 0.0f, tr = 0.0f;
        #pragma unroll
        for (int i = 0; i < 8; i++) { td += sD[i]; tr += sR[i]; }
        const float invN = 1.0f / (float)NPIX;
        atomicAdd(out + b,      td * invN);
        atomicAdd(out + 16 + b, tr * invN);
    }
}

static bool make_tex(cudaTextureObject_t* t, const void* ptr, int height) {
    cudaResourceDesc rd;
    memset(&rd, 0, sizeof(rd));
    rd.resType = cudaResourceTypePitch2D;
    rd.res.pitch2D.devPtr = const_cast<void*>(ptr);
    rd.res.pitch2D.desc = cudaCreateChannelDesc<float>();
    rd.res.pitch2D.width = WW;
    rd.res.pitch2D.height = height;
    rd.res.pitch2D.pitchInBytes = WW * sizeof(float);
    cudaTextureDesc td;
    memset(&td, 0, sizeof(td));
    td.addressMode[0] = cudaAddressModeClamp;
    td.addressMode[1] = cudaAddressModeClamp;
    td.filterMode = cudaFilterModePoint;
    td.readMode = cudaReadModeElementType;
    td.normalizedCoords = 0;
    return cudaCreateTextureObject(t, &rd, &td, nullptr) == cudaSuccess;
}

extern "C" void kernel_launch(void* const* d_in, const int* in_sizes, int n_in,
                              void* d_out, int out_size)
{
    const float* depth0 = (const float*)d_in[0];
    const float* depth1 = (const float*)d_in[1];
    const float* R0     = (const float*)d_in[2];
    const float* t0     = (const float*)d_in[3];
    const float* R1     = (const float*)d_in[4];
    const float* t1     = (const float*)d_in[5];
    const float* rgb0   = (const float*)d_in[6];
    const float* rgb1   = (const float*)d_in[7];
    const void*  mask0  = d_in[8];
    const void*  mask1  = d_in[9];
    const float* K      = (const float*)d_in[10];
    float* out = (float*)d_out;

    setup_kernel<<<1, 64>>>(R0, t0, R1, t1, K, (const unsigned int*)mask0, out, out_size);

    static cudaTextureObject_t texD0 = 0, texD1 = 0, texR0 = 0, texR1 = 0;
    static const void* cached_d0 = nullptr;
    bool ok;
    if (cached_d0 == (const void*)depth0 && texD0) {
        ok = true;  // reuse objects created on a previous call for the same buffers
    } else {
        ok = make_tex(&texD0, depth0, HH * BS)
          && make_tex(&texD1, depth1, HH * BS)
          && make_tex(&texR0, rgb0, HH * BS * 3)
          && make_tex(&texR1, rgb1, HH * BS * 3);
        if (ok) cached_d0 = (const void*)depth0;
    }

    dim3 grid(46, BS, 2);
    if (ok) {
        loss_tex_kernel<<<grid, 256>>>(depth0, depth1, rgb0, rgb1, mask0, mask1,
                                       texD0, texD1, texR0, texR1, out);
    } else {
        loss_kernel<<<grid, 256>>>(depth0, depth1, rgb0, rgb1, mask0, mask1, out);
    }
}

// round 17
// speedup vs baseline: 1.5304x; 1.0241x over previous
#include <cuda_runtime.h>
#include <cstring>

#define HH 512
#define WW 512
#define NPIX (HH*WW)
#define BS 16

__device__ float g_params[BS * 2][12];
__device__ int g_maskmode;  // 0 = 4-byte elements, 1 = 1-byte elements

__global__ void setup_kernel(const float* __restrict__ R0, const float* __restrict__ t0,
                             const float* __restrict__ R1, const float* __restrict__ t1,
                             const float* __restrict__ K,
                             const unsigned int* __restrict__ mask_probe,
                             float* __restrict__ out, int out_size)
{
    int t = threadIdx.x;
    if (t < out_size && t < 32) out[t] = 0.0f;

    if (t == 0) {
        bool sawFloat = false, sawBig = false;
        for (int i = 0; i < 16; i++) {
            unsigned int w = mask_probe[i];
            if (w == 0x3f800000u) sawFloat = true;
            else if (w > 1u) sawBig = true;
        }
        g_maskmode = sawFloat ? 0 : (sawBig ? 1 : 0);
    }

    if (t >= 32) return;
    int b = t >> 1;
    int dir = t & 1;

    float k[9];
    #pragma unroll
    for (int i = 0; i < 9; i++) k[i] = K[i];
    float det = k[0]*(k[4]*k[8]-k[5]*k[7]) - k[1]*(k[3]*k[8]-k[5]*k[6]) + k[2]*(k[3]*k[7]-k[4]*k[6]);
    float rdet = 1.0f / det;
    float ki[9];
    ki[0]=(k[4]*k[8]-k[5]*k[7])*rdet; ki[1]=(k[2]*k[7]-k[1]*k[8])*rdet; ki[2]=(k[1]*k[5]-k[2]*k[4])*rdet;
    ki[3]=(k[5]*k[6]-k[3]*k[8])*rdet; ki[4]=(k[0]*k[8]-k[2]*k[6])*rdet; ki[5]=(k[2]*k[3]-k[0]*k[5])*rdet;
    ki[6]=(k[3]*k[7]-k[4]*k[6])*rdet; ki[7]=(k[1]*k[6]-k[0]*k[7])*rdet; ki[8]=(k[0]*k[4]-k[1]*k[3])*rdet;

    const float* Ra = dir ? (R1 + 9*b) : (R0 + 9*b);
    const float* Rb = dir ? (R0 + 9*b) : (R1 + 9*b);
    const float* ta = dir ? (t1 + 3*b) : (t0 + 3*b);
    const float* tb = dir ? (t0 + 3*b) : (t1 + 3*b);

    float M3[9];
    #pragma unroll
    for (int i = 0; i < 3; i++)
        #pragma unroll
        for (int j = 0; j < 3; j++) {
            float s = 0.0f;
            #pragma unroll
            for (int d = 0; d < 3; d++) s += Rb[i*3+d] * Ra[j*3+d];
            M3[i*3+j] = s;
        }
    float M[9];
    #pragma unroll
    for (int i = 0; i < 3; i++)
        #pragma unroll
        for (int j = 0; j < 3; j++) {
            float s = 0.0f;
            #pragma unroll
            for (int d = 0; d < 3; d++) s += k[i*3+d] * M3[d*3+j];
            M[i*3+j] = s;
        }
    float c[3];
    #pragma unroll
    for (int i = 0; i < 3; i++) {
        float s = 0.0f;
        #pragma unroll
        for (int d = 0; d < 3; d++) s += k[i*3+d]*tb[d] - M[i*3+d]*ta[d];
        c[i] = s;
    }
    float G[9];
    #pragma unroll
    for (int i = 0; i < 3; i++)
        #pragma unroll
        for (int j = 0; j < 3; j++) {
            float s = 0.0f;
            #pragma unroll
            for (int d = 0; d < 3; d++) s += M[i*3+d] * ki[d*3+j];
            G[i*3+j] = s;
        }

    float* P = g_params[t];
    P[0] = G[0]; P[1] = G[3]; P[2] = G[6];
    P[3] = G[1]; P[4] = G[4]; P[5] = G[7];
    P[6] = G[2]; P[7] = G[5]; P[8] = G[8];
    P[9] = c[0]; P[10] = c[1]; P[11] = c[2];
}

__inline__ __device__ float warp_sum(float v) {
    #pragma unroll
    for (int o = 16; o > 0; o >>= 1) v += __shfl_down_sync(0xffffffffu, v, o);
    return v;
}

__inline__ __device__ float fast_rcp(float x) {
    float r;
    asm("rcp.approx.ftz.f32 %0, %1;" : "=f"(r) : "f"(x));
    return r;
}

__inline__ __device__ int load_mask_bits(const void* ms, int mode, int base, int q) {
    if (mode) {
        uchar4 u = __ldcs((const uchar4*)((const unsigned char*)ms + base) + q);
        return (u.x != 0) | ((u.y != 0) << 1) | ((u.z != 0) << 2) | ((u.w != 0) << 3);
    } else {
        uint4 u = __ldcs((const uint4*)((const unsigned int*)ms + base) + q);
        return (u.x != 0u) | ((u.y != 0u) << 1) | ((u.z != 0u) << 2) | ((u.w != 0u) << 3);
    }
}

// ============ texture-gather loss kernel with warp-compacted RGB phase ============
// Depth: 1 TLD4 per masked pixel (exact weights, nudged coords for selection only).
// RGB: passing pixels (≈13%) are compacted per-warp into a smem ring; processed
// in dense batches of 32 so the 3 TLD4 + 3 LDG run at full lane efficiency.
__global__ __launch_bounds__(256, 5)
void loss_tex_kernel(const float* __restrict__ d0, const float* __restrict__ d1,
                     const float* __restrict__ r0, const float* __restrict__ r1,
                     const void* __restrict__ m0, const void* __restrict__ m1,
                     cudaTextureObject_t texD0, cudaTextureObject_t texD1,
                     cudaTextureObject_t texR0, cudaTextureObject_t texR1,
                     float* __restrict__ out)
{
    const int b   = blockIdx.y;
    const int dir = blockIdx.z;

    const float* ds = dir ? d1 : d0;
    const float* rs = dir ? r1 : r0;
    const void*  ms = dir ? m1 : m0;
    cudaTextureObject_t texD = dir ? texD0 : texD1;   // gather-dest depth
    cudaTextureObject_t texR = dir ? texR0 : texR1;   // gather-dest rgb

    const float* P = g_params[b*2 + dir];
    const float Au0=P[0], Au1=P[1], Au2=P[2];
    const float Av0=P[3], Av1=P[4], Av2=P[5];
    const float A00=P[6], A01=P[7], A02=P[8];
    const float c0 =P[9], c1 =P[10], c2 =P[11];
    const int mode = g_maskmode;

    const int base  = b * NPIX;
    const int base3 = b * 3 * NPIX;
    const float ybD = 512.0f * (float)b;          // depth plane offset
    const float ybR = 1536.0f * (float)b;         // rgb plane-group offset

    const float4* dsv = (const float4*)(ds + base);

    // Per-warp compaction ring: 64 entries x 5 words x 8 warps = 10KB
    __shared__ float bTX[8][64], bTY[8][64], bFX[8][64], bFY[8][64];
    __shared__ int   bP [8][64];

    const int lane = threadIdx.x & 31;
    const int wwid = threadIdx.x >> 5;
    int cnt = 0;                                   // warp-uniform pending count

    float sd = 0.0f, sr = 0.0f;
    const int nq = NPIX / 4;
    const int stride = gridDim.x * blockDim.x;

    int q = blockIdx.x * blockDim.x + threadIdx.x;
    float4 dep4;
    int mb = 0;
    if (q < nq) {
        dep4 = __ldcs(dsv + q);
        mb = load_mask_bits(ms, mode, base, q);
    }

    for (; q < nq; ) {
        const int p0 = q << 2;
        float dep[4] = {dep4.x, dep4.y, dep4.z, dep4.w};

        const float v  = (float)(p0 >> 9);
        const float u0 = (float)(p0 & 511);
        const float bX = fmaf(Av0, v, A00);
        const float bY = fmaf(Av1, v, A01);
        const float bZ = fmaf(Av2, v, A02);

        float Z[4], fx[4], fy[4], tx[4], ty[4];
        #pragma unroll
        for (int i = 0; i < 4; i++) {
            float u = u0 + (float)i;
            float X  = fmaf(dep[i], fmaf(Au0, u, bX), c0);
            float Y  = fmaf(dep[i], fmaf(Au1, u, bY), c1);
            float Zi = fmaf(dep[i], fmaf(Au2, u, bZ), c2);
            Z[i] = Zi;

            float inv = fast_rcp(fmaxf(Zi, 0.0f) + 1e-12f);
            float xs = fmaf(X * inv, 512.0f / 511.0f, -0.5f);
            float ys = fmaf(Y * inv, 512.0f / 511.0f, -0.5f);
            xs = fminf(fmaxf(xs, 0.0f), 510.9995f);
            ys = fminf(fmaxf(ys, 0.0f), 510.9995f);

            float x0f = floorf(xs), y0f = floorf(ys);
            float fxi = xs - x0f, fyi = ys - y0f;
            fx[i] = fxi;                          // EXACT weights
            fy[i] = fyi;
            float cfx = fminf(fmaxf(fxi, 0.015625f), 0.984375f);
            float cfy = fminf(fmaxf(fyi, 0.015625f), 0.984375f);
            tx[i] = x0f + cfx + 0.5f;             // selection-only nudge
            ty[i] = y0f + cfy + 0.5f;
        }

        // ---- prefetch next iteration's coherent loads ----
        const int qn = q + stride;
        float4 dep4n = dep4;
        int mbn = 0;
        if (qn < nq) {
            dep4n = __ldcs(dsv + qn);
            mbn = load_mask_bits(ms, mode, base, qn);
        }

        // ---- depth: ONE TLD4 per masked pixel ----
        float4 g[4];
        #pragma unroll
        for (int i = 0; i < 4; i++) {
            if (mb & (1 << i)) {
                g[i] = tex2Dgather<float4>(texD, tx[i], ty[i] + ybD, 0);
            } else {
                g[i] = make_float4(1e30f, 1e30f, 1e30f, 1e30f);
            }
        }

        // ---- clamp test; enqueue passing pixels; dense-process full batches ----
        #pragma unroll
        for (int i = 0; i < 4; i++) {
            float ofx = 1.0f - fx[i], ofy = 1.0f - fy[i];
            float w00 = ofx*ofy, w01 = fx[i]*ofy, w10 = ofx*fy[i], w11 = fx[i]*fy[i];
            // gather component order: x=(i0,j1) y=(i1,j1) z=(i1,j0) w=(i0,j0)
            float dsm = w00*g[i].w + w01*g[i].z + w10*g[i].x + w11*g[i].y;
            float ld = fabsf(Z[i] - dsm);
            bool pass = ld < 0.1f;                // sentinel auto-fails
            sd += pass ? ld : 0.0f;

            unsigned bal = __ballot_sync(0xffffffffu, pass);
            if (pass) {
                int idx = cnt + __popc(bal & ((1u << lane) - 1u));
                bTX[wwid][idx] = tx[i];
                bTY[wwid][idx] = ty[i];
                bFX[wwid][idx] = fx[i];
                bFY[wwid][idx] = fy[i];
                bP [wwid][idx] = p0 + i;
            }
            cnt += __popc(bal);

            if (cnt >= 32) {
                cnt -= 32;
                int idx = cnt + lane;
                float txe = bTX[wwid][idx], tye = bTY[wwid][idx];
                float fxe = bFX[wwid][idx], fye = bFY[wwid][idx];
                int   pe  = bP [wwid][idx];
                float oxe = 1.0f - fxe, oye = 1.0f - fye;
                float e00 = oxe*oye, e01 = fxe*oye, e10 = oxe*fye, e11 = fxe*fye;
                float lr = 0.0f;
                #pragma unroll
                for (int cch = 0; cch < 3; cch++) {
                    float sv = __ldg(rs + base3 + cch * NPIX + pe);
                    float4 gc = tex2Dgather<float4>(texR, txe, tye + ybR + 512.0f*(float)cch, 0);
                    float sm = e00*gc.w + e01*gc.z + e10*gc.x + e11*gc.y;
                    lr += fabsf(sv - sm);
                }
                sr += lr * (1.0f / 3.0f);
            }
        }

        dep4 = dep4n;
        mb = mbn;
        q = qn;
    }

    // ---- flush remaining (<32) compacted entries ----
    if (lane < cnt) {
        float txe = bTX[wwid][lane], tye = bTY[wwid][lane];
        float fxe = bFX[wwid][lane], fye = bFY[wwid][lane];
        int   pe  = bP [wwid][lane];
        float oxe = 1.0f - fxe, oye = 1.0f - fye;
        float e00 = oxe*oye, e01 = fxe*oye, e10 = oxe*fye, e11 = fxe*fye;
        float lr = 0.0f;
        #pragma unroll
        for (int cch = 0; cch < 3; cch++) {
            float sv = __ldg(rs + base3 + cch * NPIX + pe);
            float4 gc = tex2Dgather<float4>(texR, txe, tye + ybR + 512.0f*(float)cch, 0);
            float sm = e00*gc.w + e01*gc.z + e10*gc.x + e11*gc.y;
            lr += fabsf(sv - sm);
        }
        sr += lr * (1.0f / 3.0f);
    }

    sd = warp_sum(sd);
    sr = warp_sum(sr);
    __shared__ float sD[8], sR[8];
    if (lane == 0) { sD[wwid] = sd; sR[wwid] = sr; }
    __syncthreads();
    if (threadIdx.x == 0) {
        float td = 0.0f, tr = 0.0f;
        #pragma unroll
        for (int i = 0; i < 8; i++) { td += sD[i]; tr += sR[i]; }
        const float invN = 1.0f / (float)NPIX;
        atomicAdd(out + b,      td * invN);
        atomicAdd(out + 16 + b, tr * invN);
    }
}

// ============ fallback: proven R9 LDG kernel ============
__global__ __launch_bounds__(256, 5)
void loss_kernel(const float* __restrict__ d0, const float* __restrict__ d1,
                 const float* __restrict__ r0, const float* __restrict__ r1,
                 const void* __restrict__ m0, const void* __restrict__ m1,
                 float* __restrict__ out)
{
    const int b   = blockIdx.y;
    const int dir = blockIdx.z;

    const float* ds = dir ? d1 : d0;
    const float* dd = dir ? d0 : d1;
    const float* rs = dir ? r1 : r0;
    const float* rd = dir ? r0 : r1;
    const void*  ms = dir ? m1 : m0;

    const float* P = g_params[b*2 + dir];
    const float Au0=P[0], Au1=P[1], Au2=P[2];
    const float Av0=P[3], Av1=P[4], Av2=P[5];
    const float A00=P[6], A01=P[7], A02=P[8];
    const float c0 =P[9], c1 =P[10], c2 =P[11];
    const int mode = g_maskmode;

    const int base  = b * NPIX;
    const int base3 = b * 3 * NPIX;
    const float4* dsv = (const float4*)(ds + base);

    float sd = 0.0f, sr = 0.0f;
    const int nq = NPIX / 4;
    const int stride = gridDim.x * blockDim.x;

    int q = blockIdx.x * blockDim.x + threadIdx.x;
    float4 dep4;
    int mb = 0;
    if (q < nq) {
        dep4 = __ldcs(dsv + q);
        mb = load_mask_bits(ms, mode, base, q);
    }

    for (; q < nq; ) {
        const int p0 = q << 2;
        float dep[4] = {dep4.x, dep4.y, dep4.z, dep4.w};

        const float v  = (float)(p0 >> 9);
        const float u0 = (float)(p0 & 511);
        const float bX = fmaf(Av0, v, A00);
        const float bY = fmaf(Av1, v, A01);
        const float bZ = fmaf(Av2, v, A02);

        float Z[4], fx[4], fy[4];
        int i00[4];
        #pragma unroll
        for (int i = 0; i < 4; i++) {
            float u = u0 + (float)i;
            float X  = fmaf(dep[i], fmaf(Au0, u, bX), c0);
            float Y  = fmaf(dep[i], fmaf(Au1, u, bY), c1);
            float Zi = fmaf(dep[i], fmaf(Au2, u, bZ), c2);
            Z[i] = Zi;

            float inv = fast_rcp(fmaxf(Zi, 0.0f) + 1e-12f);
            float xs = fmaf(X * inv, 512.0f / 511.0f, -0.5f);
            float ys = fmaf(Y * inv, 512.0f / 511.0f, -0.5f);
            xs = fminf(fmaxf(xs, 0.0f), 510.9995f);
            ys = fminf(fmaxf(ys, 0.0f), 510.9995f);

            float x0f = floorf(xs), y0f = floorf(ys);
            fx[i] = xs - x0f;
            fy[i] = ys - y0f;
            i00[i] = base + (int)y0f * WW + (int)x0f;
        }

        const int qn = q + stride;
        float4 dep4n = dep4;
        int mbn = 0;
        if (qn < nq) {
            dep4n = __ldcs(dsv + qn);
            mbn = load_mask_bits(ms, mode, base, qn);
        }

        float g00[4], g01[4], g10[4], g11[4];
        #pragma unroll
        for (int i = 0; i < 4; i++) {
            if (mb & (1 << i)) {
                const float* a = dd + i00[i];
                g00[i] = __ldg(a);
                g01[i] = __ldg(a + 1);
                g10[i] = __ldg(a + WW);
                g11[i] = __ldg(a + WW + 1);
            } else {
                g00[i] = g01[i] = g10[i] = g11[i] = 1e30f;
            }
        }

        #pragma unroll
        for (int i = 0; i < 4; i++) {
            float ofx = 1.0f - fx[i], ofy = 1.0f - fy[i];
            float w00 = ofx*ofy, w01 = fx[i]*ofy, w10 = ofx*fy[i], w11 = fx[i]*fy[i];
            float dsm = w00*g00[i] + w01*g01[i] + w10*g10[i] + w11*g11[i];
            float ld = fabsf(Z[i] - dsm);
            if (ld < 0.1f) {
                sd += ld;
                int a00 = i00[i] - base;
                int p = p0 + i;
                float lr = 0.0f;
                #pragma unroll
                for (int cch = 0; cch < 3; cch++) {
                    const int o = base3 + cch * NPIX;
                    float sv = __ldcs(rs + o + p);
                    const float* ch = rd + o + a00;
                    float sm = w00*__ldg(ch)      + w01*__ldg(ch + 1)
                             + w10*__ldg(ch + WW) + w11*__ldg(ch + WW + 1);
                    lr += fabsf(sv - sm);
                }
                sr += lr * (1.0f / 3.0f);
            }
        }

        dep4 = dep4n;
        mb = mbn;
        q = qn;
    }

    sd = warp_sum(sd);
    sr = warp_sum(sr);
    __shared__ float sD[8], sR[8];
    int lane = threadIdx.x & 31, wid = threadIdx.x >> 5;
    if (lane == 0) { sD[wid] = sd; sR[wid] = sr; }
    __syncthreads();
    if (threadIdx.x == 0) {
        float td = 0.0f, tr = 0.0f;
        #pragma unroll
        for (int i = 0; i < 8; i++) { td += sD[i]; tr += sR[i]; }
        const float invN = 1.0f / (float)NPIX;
        atomicAdd(out + b,      td * invN);
        atomicAdd(out + 16 + b, tr * invN);
    }
}

static bool make_tex(cudaTextureObject_t* t, const void* ptr, int height) {
    cudaResourceDesc rd;
    memset(&rd, 0, sizeof(rd));
    rd.resType = cudaResourceTypePitch2D;
    rd.res.pitch2D.devPtr = const_cast<void*>(ptr);
    rd.res.pitch2D.desc = cudaCreateChannelDesc<float>();
    rd.res.pitch2D.width = WW;
    rd.res.pitch2D.height = height;
    rd.res.pitch2D.pitchInBytes = WW * sizeof(float);
    cudaTextureDesc td;
    memset(&td, 0, sizeof(td));
    td.addressMode[0] = cudaAddressModeClamp;
    td.addressMode[1] = cudaAddressModeClamp;
    td.filterMode = cudaFilterModePoint;
    td.readMode = cudaReadModeElementType;
    td.normalizedCoords = 0;
    return cudaCreateTextureObject(t, &rd, &td, nullptr) == cudaSuccess;
}

extern "C" void kernel_launch(void* const* d_in, const int* in_sizes, int n_in,
                              void* d_out, int out_size)
{
    const float* depth0 = (const float*)d_in[0];
    const float* depth1 = (const float*)d_in[1];
    const float* R0     = (const float*)d_in[2];
    const float* t0     = (const float*)d_in[3];
    const float* R1     = (const float*)d_in[4];
    const float* t1     = (const float*)d_in[5];
    const float* rgb0   = (const float*)d_in[6];
    const float* rgb1   = (const float*)d_in[7];
    const void*  mask0  = d_in[8];
    const void*  mask1  = d_in[9];
    const float* K      = (const float*)d_in[10];
    float* out = (float*)d_out;

    setup_kernel<<<1, 64>>>(R0, t0, R1, t1, K, (const unsigned int*)mask0, out, out_size);

    static cudaTextureObject_t texD0 = 0, texD1 = 0, texR0 = 0, texR1 = 0;
    static const void* cached_d0 = nullptr;
    bool ok;
    if (cached_d0 == (const void*)depth0 && texD0) {
        ok = true;  // reuse objects created on a previous call for the same buffers
    } else {
        ok = make_tex(&texD0, depth0, HH * BS)
          && make_tex(&texD1, depth1, HH * BS)
          && make_tex(&texR0, rgb0, HH * BS * 3)
          && make_tex(&texR1, rgb1, HH * BS * 3);
        if (ok) cached_d0 = (const void*)depth0;
    }

    dim3 grid(46, BS, 2);
    if (ok) {
        loss_tex_kernel<<<grid, 256>>>(depth0, depth1, rgb0, rgb1, mask0, mask1,
                                       texD0, texD1, texR0, texR1, out);
    } else {
        loss_kernel<<<grid, 256>>>(depth0, depth1, rgb0, rgb1, mask0, mask1, out);
    }
}